// round 13
// baseline (speedup 1.0000x reference)
#include <cuda_runtime.h>
#include <stdint.h>

// MyDropout: out = x * mask; mask = JAX partitionable-threefry dropout
// (seed 42, p=0.1), columns < 64 zeroed. x: [16384, 4096] f32, N = 67108864.
//
//   bits(i) = o0 ^ o1, (o0,o1) = threefry2x32(key=(0,42), ctr=(0,i))
//   keep  <=>  bits < 0xE6666600
//
// alu pipe is the roofline (40 SHF+LOP3 ops/elem at f=0). This round: 5 of
// the 20 rotates (all r=13 and r=17) are computed as a MUL-PAIR on the fma
// pipe -- lo = v*m (IMAD.LO), hi = __umulhi(v,m) (IMAD.HI), m = 2^r passed
// as an opaque kernel param -- leaving one LOP3 (lo|hi)^x0 on alu. Unlike
// round-8's IMAD.WIDE these are independent 32-bit ops (no register pairs).
// Per-elem: alu 40->35, fma 21->31, issue ~34->36.5 units; balanced pipes.

#define TF_ROT(x, r) (((x) << (r)) | ((x) >> (32 - (r))))

// Add forced onto the fma pipe: IMAD Rd, Ra, one, Rb (`one` opaque to ptxas).
#define FADDU(a, b) ((a) * one + (b))

// SHF-form round: add(fma) + SHF(alu) + LOP3(alu).
#define RND_S(r) do { x0 = FADDU(x0, x1); x1 = TF_ROT(x1, r) ^ x0; } while (0)

// MUL-form round: add(fma) + IMAD.LO(fma) + IMAD.HI(fma) + LOP3(alu).
#define RND_M(m) do { \
    x0 = FADDU(x0, x1); \
    x1 = ((x1 * (m)) | __umulhi(x1, (m))) ^ x0; \
} while (0)

__device__ __forceinline__ uint32_t tf_bits(uint32_t i, uint32_t one,
                                            uint32_t m13, uint32_t m17) {
    const uint32_t k1 = 42u;
    const uint32_t k2 = 0x1BD11BF0u;   // 0x1BD11BDA ^ 0 ^ 42

    uint32_t x1 = FADDU(i, k1);        // ctr_lo + k1  (IMAD)
    uint32_t x0 = x1;                  // round-1 add: x0 = 0 + x1
    x1 = ((x1 * m13) | __umulhi(x1, m13)) ^ x0;   // round 1 rot13 (mul-form)
    RND_S(15); RND_S(26); RND_S(6);
    x0 = FADDU(x0, k1); x1 = FADDU(x1, k2 + 1u);
    RND_M(m17); RND_S(29); RND_S(16); RND_S(24);
    x0 = FADDU(x0, k2); x1 = FADDU(x1, 2u);          // k0 = 0
    RND_M(m13); RND_S(15); RND_S(26); RND_S(6);
    x1 = FADDU(x1, k1 + 3u);                          // x0 += k0 is a no-op
    RND_M(m17); RND_S(29); RND_S(16); RND_S(24);
    x0 = FADDU(x0, k1); x1 = FADDU(x1, k2 + 4u);
    RND_M(m13); RND_S(15); RND_S(26); RND_S(6);
    x0 = FADDU(x0, k2); x1 = FADDU(x1, 5u);          // k0 = 0
    return x0 ^ x1;                    // partitionable 32-bit output
}

__global__ __launch_bounds__(256) void mydropout_kernel(
    const float4* __restrict__ x, float4* __restrict__ out,
    uint32_t one, uint32_t m13, uint32_t m17) {
    const uint32_t KEEP_LT = 0xE6666600u;   // bits < this  <=>  keep (u < 0.9f)
    const float scale = (float)(1.0 / 0.9);

    uint32_t tid = blockIdx.x * blockDim.x + threadIdx.x;  // one float4 / thread
    uint32_t g = tid << 2;                                 // element index
    uint32_t col = g & 4095u;                              // column (row = 4096)

    if (col < 64u) {
        // K=64 leading columns zeroed; float4-aligned, whole vector is zero.
        out[tid] = make_float4(0.f, 0.f, 0.f, 0.f);
        return;
    }

    float4 a = x[tid];

    uint32_t b0 = tf_bits(g + 0u, one, m13, m17);
    uint32_t b1 = tf_bits(g + 1u, one, m13, m17);
    uint32_t b2 = tf_bits(g + 2u, one, m13, m17);
    uint32_t b3 = tf_bits(g + 3u, one, m13, m17);

    float4 r;
    r.x = a.x * ((b0 < KEEP_LT) ? scale : 0.f);
    r.y = a.y * ((b1 < KEEP_LT) ? scale : 0.f);
    r.z = a.z * ((b2 < KEEP_LT) ? scale : 0.f);
    r.w = a.w * ((b3 < KEEP_LT) ? scale : 0.f);

    out[tid] = r;
}

extern "C" void kernel_launch(void* const* d_in, const int* in_sizes, int n_in,
                              void* d_out, int out_size) {
    const float4* x = (const float4*)d_in[0];
    float4* out = (float4*)d_out;
    const int threads = 256;
    const int blocks = 16777216 / threads;  // N/4 threads
    // Opaque constants: `one` keeps adds on IMAD (fma pipe); m13/m17 keep the
    // mul-pair rotates as real IMAD.LO/HI instead of folding back to SHF.
    mydropout_kernel<<<blocks, threads>>>(x, out, 1u, 1u << 13, 1u << 17);
}